// round 13
// baseline (speedup 1.0000x reference)
#include <cuda_runtime.h>
#include <cuda_bf16.h>
#include <cstdint>

// PlaneModel: B=8192, NS=32, P=64, HID1=16, BASE=32, OUT=13, D_IN=79
// Layer-1 GEMV on mma.sync m16n8k16 bf16, hi/lo-pair split, fp32 accum.
// warp = batch. Early block-sync (tables only), warp-private gather, parallel-LN.
#define FULL 0xffffffffu
#define ZS 84        // word stride: frag reads conflict-free
#define BSTR 24      // B table stride: conflict-free frag reads

__device__ __forceinline__ uint32_t packsplit(float v){
    __nv_bfloat16 h = __float2bfloat16_rn(v);
    float hf = __bfloat162float(h);
    __nv_bfloat16 l = __float2bfloat16_rn(v - hf);
    uint16_t hu = *(uint16_t*)&h, lu = *(uint16_t*)&l;
    return (uint32_t)hu | ((uint32_t)lu << 16);
}
__device__ __forceinline__ void mma16(float* d, const uint32_t* a, const uint32_t* b){
    asm volatile("mma.sync.aligned.m16n8k16.row.col.f32.bf16.bf16.f32 "
        "{%0,%1,%2,%3},{%4,%5,%6,%7},{%8,%9},{%0,%1,%2,%3};"
        : "+f"(d[0]), "+f"(d[1]), "+f"(d[2]), "+f"(d[3])
        : "r"(a[0]), "r"(a[1]), "r"(a[2]), "r"(a[3]), "r"(b[0]), "r"(b[1]));
}
// parallel two-value butterfly over the full warp
__device__ __forceinline__ void wsum2(float& x, float& y){
    x += __shfl_xor_sync(FULL, x, 16);  y += __shfl_xor_sync(FULL, y, 16);
    x += __shfl_xor_sync(FULL, x, 8);   y += __shfl_xor_sync(FULL, y, 8);
    x += __shfl_xor_sync(FULL, x, 4);   y += __shfl_xor_sync(FULL, y, 4);
    x += __shfl_xor_sync(FULL, x, 2);   y += __shfl_xor_sync(FULL, y, 2);
    x += __shfl_xor_sync(FULL, x, 1);   y += __shfl_xor_sync(FULL, y, 1);
}

__global__ void __launch_bounds__(256)
plane_kernel(const float* __restrict__ g_pos,  const float* __restrict__ g_quat,
             const float* __restrict__ g_xz,   const float* __restrict__ g_aabb,
             const int*   __restrict__ g_widx, const float* __restrict__ g_pls,
             const float* __restrict__ g_w1,   const float* __restrict__ g_b1,
             const float* __restrict__ g_g1,   const float* __restrict__ g_be1,
             const float* __restrict__ g_w2a,  const float* __restrict__ g_b2a,
             const float* __restrict__ g_g2a,  const float* __restrict__ g_be2a,
             const float* __restrict__ g_w2b,  const float* __restrict__ g_b2b,
             const float* __restrict__ g_g2b,  const float* __restrict__ g_be2b,
             const float* __restrict__ g_wout, const float* __restrict__ g_bout,
             float* __restrict__ g_out)
{
    extern __shared__ __align__(16) uint32_t smw[];
    uint32_t* s_b1 = smw;               // 80*24 packed (bhi,bhi) [k][n]
    uint32_t* s_b2 = s_b1 + 80*BSTR;    // 80*24 packed (blo, 0 )
    float*    s_v  = (float*)(s_b2 + 80*BSTR);   // 8*16 per-warp layer-1 sums
    uint32_t* s_z  = (uint32_t*)(s_v + 128);     // 8 * 32*ZS packed A words

    const int tid  = threadIdx.x;
    const int warp = tid >> 5, lane = tid & 31;
    const int j    = lane & 3;
    const int gr   = lane >> 2;
    const int b    = (blockIdx.x << 3) + warp;
    uint32_t* szw = s_z + warp*(32*ZS);

    // ---- prefetch per-batch scalars (overlap the table-build LDGs) ----
    const int idx = __ldg(g_widx + b*32 + lane);
    float qx = __ldg(g_quat + b*4 + 0), qy = __ldg(g_quat + b*4 + 1);
    float qz = __ldg(g_quat + b*4 + 2), qw = __ldg(g_quat + b*4 + 3);
    float px = __ldg(g_pos + b*3 + 0), py = __ldg(g_pos + b*3 + 1), pz = __ldg(g_pos + b*3 + 2);
    float lox = __ldg(g_aabb + b*6 + 0), loy = __ldg(g_aabb + b*6 + 1), loz = __ldg(g_aabb + b*6 + 2);
    float hix = __ldg(g_aabb + b*6 + 3), hiy = __ldg(g_aabb + b*6 + 4), hiz = __ldg(g_aabb + b*6 + 5);
    float epl = __expf(__ldg(g_pls));

    // ---- B tables (feature-permuted: xz 0..63, pick 64..66, pose 67..78, 79=0) ----
    for (int e = tid; e < 1280; e += 256){
        int k = e >> 4, n = e & 15;
        float w = 0.f;
        if (k < 79){
            int f = (k < 64) ? k + 3 : ((k < 67) ? k - 64 : k);
            w = __ldg(g_w1 + f*16 + n);
        }
        __nv_bfloat16 h = __float2bfloat16_rn(w);
        float hf = __bfloat162float(h);
        __nv_bfloat16 l = __float2bfloat16_rn(w - hf);
        uint16_t hu = *(uint16_t*)&h, lu = *(uint16_t*)&l;
        s_b1[k*BSTR + n] = (uint32_t)hu | ((uint32_t)hu << 16);
        s_b2[k*BSTR + n] = (uint32_t)lu;
    }
    __syncthreads();   // EARLY: only the shared tables need block scope

    // ---- warp-private gather: pack hi/lo at staging time ----
    const float* xzb = g_xz + ((size_t)b << 15);
    #pragma unroll
    for (int r = 0; r < 32; r++){
        int ir = __shfl_sync(FULL, idx, r);
        const float* src = xzb + (ir << 6);
        szw[r*ZS + lane]      = packsplit(__ldcs(src + lane));
        szw[r*ZS + 32 + lane] = packsplit(__ldcs(src + 32 + lane));
    }

    // ---- pose features -> words 64..79 (row = lane) ----
    {
        float rn = rsqrtf(qx*qx + qy*qy + qz*qz + qw*qw);
        qx *= rn; qy *= rn; qz *= rn; qw *= rn;
        float r00 = 1.f - 2.f*(qy*qy + qz*qz), r01 = 2.f*(qx*qy - qz*qw), r02 = 2.f*(qx*qz + qy*qw);
        float r10 = 2.f*(qx*qy + qz*qw), r11 = 1.f - 2.f*(qx*qx + qz*qz), r12 = 2.f*(qy*qz - qx*qw);
        float r20 = 2.f*(qx*qz - qy*qw), r21 = 2.f*(qy*qz + qx*qw), r22 = 1.f - 2.f*(qx*qx + qy*qy);
        float ci = (float)(idx >> 6) + 0.5f, cj = (float)((idx >> 3) & 7) + 0.5f, ck = (float)(idx & 7) + 0.5f;
        float vx = (ci*0.125f)*(hix - lox) + lox;
        float vy = (cj*0.125f)*(hiy - loy) + loy;
        float vz = (ck*0.125f)*(hiz - loz) + loz;
        uint32_t* prow = szw + lane*ZS;
        prow[64] = packsplit(r00*vx + r01*vy + r02*vz + px);
        prow[65] = packsplit(r10*vx + r11*vy + r12*vz + py);
        prow[66] = packsplit(r20*vx + r21*vy + r22*vz + pz);
        prow[67] = packsplit(px*epl); prow[68] = packsplit(py*epl); prow[69] = packsplit(pz*epl);
        prow[70] = packsplit(r00); prow[71] = packsplit(r01); prow[72] = packsplit(r02);
        prow[73] = packsplit(r10); prow[74] = packsplit(r11); prow[75] = packsplit(r12);
        prow[76] = packsplit(r20); prow[77] = packsplit(r21); prow[78] = packsplit(r22);
        prow[79] = 0u;
    }
    __syncwarp(FULL);

    // ---- bf16 MMA: 10 chunks x 2 mt x 2 nt x 2 passes, 8 independent chains ----
    float dA[2][2][4], dB[2][2][4];
    #pragma unroll
    for (int mt = 0; mt < 2; mt++)
        #pragma unroll
        for (int nt = 0; nt < 2; nt++)
            #pragma unroll
            for (int q = 0; q < 4; q++){ dA[mt][nt][q] = 0.f; dB[mt][nt][q] = 0.f; }

    #pragma unroll
    for (int k0 = 0; k0 < 10; k0++){
        const int kA = k0*8 + j;
        uint32_t b1f[2][2], b2f[2][2];
        #pragma unroll
        for (int nt = 0; nt < 2; nt++){
            b1f[nt][0] = s_b1[(kA  )*BSTR + nt*8 + gr];
            b1f[nt][1] = s_b1[(kA+4)*BSTR + nt*8 + gr];
            b2f[nt][0] = s_b2[(kA  )*BSTR + nt*8 + gr];
            b2f[nt][1] = s_b2[(kA+4)*BSTR + nt*8 + gr];
        }
        #pragma unroll
        for (int mt = 0; mt < 2; mt++){
            const uint32_t* base = szw + (mt*16 + gr)*ZS + kA;
            uint32_t a[4] = { base[0], base[8*ZS], base[4], base[8*ZS + 4] };
            #pragma unroll
            for (int nt = 0; nt < 2; nt++){
                mma16(dA[mt][nt], a, b1f[nt]);
                mma16(dB[mt][nt], a, b2f[nt]);
            }
        }
    }

    float d[2][2][4];
    #pragma unroll
    for (int mt = 0; mt < 2; mt++)
        #pragma unroll
        for (int nt = 0; nt < 2; nt++)
            #pragma unroll
            for (int q = 0; q < 4; q++)
                d[mt][nt][q] = dA[mt][nt][q] + dB[mt][nt][q];

    // ---- epilogue: bias + relu + parallel-LN(16) per sample, x2, sum over samples ----
    float b1v[4] = { __ldg(g_b1 + 2*j),  __ldg(g_b1 + 2*j + 1),
                     __ldg(g_b1 + 8 + 2*j), __ldg(g_b1 + 9 + 2*j) };
    float g1v[4] = { __ldg(g_g1 + 2*j),  __ldg(g_g1 + 2*j + 1),
                     __ldg(g_g1 + 8 + 2*j), __ldg(g_g1 + 9 + 2*j) };
    float be1v[4] = { __ldg(g_be1 + 2*j), __ldg(g_be1 + 2*j + 1),
                      __ldg(g_be1 + 8 + 2*j), __ldg(g_be1 + 9 + 2*j) };

    float vsum[4] = {0.f, 0.f, 0.f, 0.f};
    #pragma unroll
    for (int mt = 0; mt < 2; mt++){
        #pragma unroll
        for (int rl = 0; rl < 2; rl++){
            float y0 = fmaxf(d[mt][0][rl*2]   + b1v[0], 0.f);
            float y1 = fmaxf(d[mt][0][rl*2+1] + b1v[1], 0.f);
            float y2 = fmaxf(d[mt][1][rl*2]   + b1v[2], 0.f);
            float y3 = fmaxf(d[mt][1][rl*2+1] + b1v[3], 0.f);
            float s  = (y0 + y1) + (y2 + y3);
            float t2 = (y0*y0 + y1*y1) + (y2*y2 + y3*y3);
            s  += __shfl_xor_sync(FULL, s, 1);   t2 += __shfl_xor_sync(FULL, t2, 1);
            s  += __shfl_xor_sync(FULL, s, 2);   t2 += __shfl_xor_sync(FULL, t2, 2);
            float m   = s * 0.0625f;
            float var = t2 * 0.0625f - m*m;
            float is2 = 2.f * rsqrtf(var + 1e-6f);   // LN then z+z
            vsum[0] += (y0 - m) * is2 * g1v[0] + 2.f*be1v[0];
            vsum[1] += (y1 - m) * is2 * g1v[1] + 2.f*be1v[1];
            vsum[2] += (y2 - m) * is2 * g1v[2] + 2.f*be1v[2];
            vsum[3] += (y3 - m) * is2 * g1v[3] + 2.f*be1v[3];
        }
    }
    #pragma unroll
    for (int c = 0; c < 4; c++){
        vsum[c] += __shfl_xor_sync(FULL, vsum[c], 4);
        vsum[c] += __shfl_xor_sync(FULL, vsum[c], 8);
        vsum[c] += __shfl_xor_sync(FULL, vsum[c], 16);
    }
    if (gr == 0){
        float* sv = s_v + warp*16;
        sv[2*j]     = vsum[0];
        sv[2*j + 1] = vsum[1];
        sv[8 + 2*j] = vsum[2];
        sv[9 + 2*j] = vsum[3];
    }
    __syncwarp(FULL);
    float v[16];
    #pragma unroll
    for (int t = 0; t < 4; t++){
        float4 s4 = *(const float4*)(s_v + warp*16 + 4*t);
        v[4*t] = s4.x; v[4*t+1] = s4.y; v[4*t+2] = s4.z; v[4*t+3] = s4.w;
    }

    // ---- head: lane = channel, parallel-LN ----
    {
        float a0 = __ldg(g_b2a + lane), a1 = 0.f, a2 = 0.f, a3 = 0.f;
        #pragma unroll
        for (int i = 0; i < 16; i += 4){
            a0 = fmaf(v[i+0], __ldg(g_w2a + (i+0)*32 + lane), a0);
            a1 = fmaf(v[i+1], __ldg(g_w2a + (i+1)*32 + lane), a1);
            a2 = fmaf(v[i+2], __ldg(g_w2a + (i+2)*32 + lane), a2);
            a3 = fmaf(v[i+3], __ldg(g_w2a + (i+3)*32 + lane), a3);
        }
        float a = (a0 + a1) + (a2 + a3);
        a = fmaxf(a, 0.f);
        float s1 = a, s2 = a*a;
        wsum2(s1, s2);
        float ma = s1 * 0.03125f;
        float va = s2 * 0.03125f - ma*ma;
        float ya = (a - ma) * rsqrtf(va + 1e-6f) * __ldg(g_g2a + lane) + __ldg(g_be2a + lane);

        float c0 = __ldg(g_b2b + lane), c1 = 0.f, c2 = 0.f, c3 = 0.f;
        #pragma unroll
        for (int i = 0; i < 32; i += 4){
            c0 = fmaf(__shfl_sync(FULL, ya, i+0), __ldg(g_w2b + (i+0)*32 + lane), c0);
            c1 = fmaf(__shfl_sync(FULL, ya, i+1), __ldg(g_w2b + (i+1)*32 + lane), c1);
            c2 = fmaf(__shfl_sync(FULL, ya, i+2), __ldg(g_w2b + (i+2)*32 + lane), c2);
            c3 = fmaf(__shfl_sync(FULL, ya, i+3), __ldg(g_w2b + (i+3)*32 + lane), c3);
        }
        float c = (c0 + c1) + (c2 + c3);
        c = fmaxf(c, 0.f);
        float u1 = c, u2 = c*c;
        wsum2(u1, u2);
        float mc = u1 * 0.03125f;
        float vc = u2 * 0.03125f - mc*mc;
        float yb = (c - mc) * rsqrtf(vc + 1e-6f) * __ldg(g_g2b + lane) + __ldg(g_be2b + lane);
        float zf = yb + ya;   // residual

        float o0 = (lane < 13) ? __ldg(g_bout + lane) : 0.f;
        float o1 = 0.f;
        #pragma unroll
        for (int i = 0; i < 32; i += 2){
            float zi0 = __shfl_sync(FULL, zf, i);
            float zi1 = __shfl_sync(FULL, zf, i+1);
            if (lane < 13){
                o0 = fmaf(zi0, __ldg(g_wout + (i  )*13 + lane), o0);
                o1 = fmaf(zi1, __ldg(g_wout + (i+1)*13 + lane), o1);
            }
        }
        if (lane < 13) g_out[b*13 + lane] = tanhf(o0 + o1);
    }
}

extern "C" void kernel_launch(void* const* d_in, const int* in_sizes, int n_in,
                              void* d_out, int out_size)
{
    (void)in_sizes; (void)n_in; (void)out_size;
    const int SMEM_BYTES = (80*BSTR*2 + 128 + 8*32*ZS) * 4;   // ~101.9 KB
    cudaFuncSetAttribute(plane_kernel,
                         cudaFuncAttributeMaxDynamicSharedMemorySize, SMEM_BYTES);
    plane_kernel<<<1024, 256, SMEM_BYTES>>>(
        (const float*)d_in[0],  (const float*)d_in[1],  (const float*)d_in[2],
        (const float*)d_in[3],  (const int*)  d_in[4],  (const float*)d_in[5],
        (const float*)d_in[6],  (const float*)d_in[7],  (const float*)d_in[8],
        (const float*)d_in[9],  (const float*)d_in[10], (const float*)d_in[11],
        (const float*)d_in[12], (const float*)d_in[13], (const float*)d_in[14],
        (const float*)d_in[15], (const float*)d_in[16], (const float*)d_in[17],
        (const float*)d_in[18], (const float*)d_in[19],
        (float*)d_out);
}

// round 14
// speedup vs baseline: 1.4715x; 1.4715x over previous
#include <cuda_runtime.h>
#include <cuda_fp16.h>
#include <cstdint>

// PlaneModel: B=8192, NS=32, P=64, HID1=16, BASE=32, OUT=13, D_IN=79
// Layer-1 GEMV on mma.sync m16n8k16 fp16 (true K=80, 5 chunks), fp32 accum.
// A = fp16 pairs; B = whi + wlo*2^11 (2 passes, recombined dA + dB/2048).
// warp = batch: 32 rows x 16 ch. ZS=44 -> 53KB smem -> 4 blocks/SM.
#define FULL 0xffffffffu
#define ZS 44        // word stride: (12*gr + j) mod 32 all-distinct -> conflict-free frag reads
#define BSTR 24      // B table stride: (24j + 8nt + gr) mod 32 distinct per instruction

__device__ __forceinline__ uint32_t pack2(float x, float y){
    __half2 h = __floats2half2_rn(x, y);
    return *(uint32_t*)&h;
}
__device__ __forceinline__ void mma16(float* d, const uint32_t* a, const uint32_t* b){
    asm volatile("mma.sync.aligned.m16n8k16.row.col.f32.f16.f16.f32 "
        "{%0,%1,%2,%3},{%4,%5,%6,%7},{%8,%9},{%0,%1,%2,%3};"
        : "+f"(d[0]), "+f"(d[1]), "+f"(d[2]), "+f"(d[3])
        : "r"(a[0]), "r"(a[1]), "r"(a[2]), "r"(a[3]), "r"(b[0]), "r"(b[1]));
}
__device__ __forceinline__ void wsum2(float& x, float& y){
    x += __shfl_xor_sync(FULL, x, 16);  y += __shfl_xor_sync(FULL, y, 16);
    x += __shfl_xor_sync(FULL, x, 8);   y += __shfl_xor_sync(FULL, y, 8);
    x += __shfl_xor_sync(FULL, x, 4);   y += __shfl_xor_sync(FULL, y, 4);
    x += __shfl_xor_sync(FULL, x, 2);   y += __shfl_xor_sync(FULL, y, 2);
    x += __shfl_xor_sync(FULL, x, 1);   y += __shfl_xor_sync(FULL, y, 1);
}

__global__ void __launch_bounds__(256)
plane_kernel(const float* __restrict__ g_pos,  const float* __restrict__ g_quat,
             const float* __restrict__ g_xz,   const float* __restrict__ g_aabb,
             const int*   __restrict__ g_widx, const float* __restrict__ g_pls,
             const float* __restrict__ g_w1,   const float* __restrict__ g_b1,
             const float* __restrict__ g_g1,   const float* __restrict__ g_be1,
             const float* __restrict__ g_w2a,  const float* __restrict__ g_b2a,
             const float* __restrict__ g_g2a,  const float* __restrict__ g_be2a,
             const float* __restrict__ g_w2b,  const float* __restrict__ g_b2b,
             const float* __restrict__ g_g2b,  const float* __restrict__ g_be2b,
             const float* __restrict__ g_wout, const float* __restrict__ g_bout,
             float* __restrict__ g_out)
{
    extern __shared__ __align__(16) uint32_t smw[];
    uint32_t* s_b1 = smw;               // 40*24 packed (whi pairs) [word][n]
    uint32_t* s_b2 = s_b1 + 40*BSTR;    // 40*24 packed (wlo*2^11 pairs)
    float*    s_v  = (float*)(s_b2 + 40*BSTR);   // 8*16 per-warp layer-1 sums
    uint32_t* s_z  = (uint32_t*)(s_v + 128);     // 8 * 32*ZS packed A words

    const int tid  = threadIdx.x;
    const int warp = tid >> 5, lane = tid & 31;
    const int j    = lane & 3;
    const int gr   = lane >> 2;
    const int b    = (blockIdx.x << 3) + warp;
    uint32_t* szw = s_z + warp*(32*ZS);

    // ---- prefetch per-batch scalars ----
    const int idx = __ldg(g_widx + b*32 + lane);
    float qx = __ldg(g_quat + b*4 + 0), qy = __ldg(g_quat + b*4 + 1);
    float qz = __ldg(g_quat + b*4 + 2), qw = __ldg(g_quat + b*4 + 3);
    float px = __ldg(g_pos + b*3 + 0), py = __ldg(g_pos + b*3 + 1), pz = __ldg(g_pos + b*3 + 2);
    float lox = __ldg(g_aabb + b*6 + 0), loy = __ldg(g_aabb + b*6 + 1), loz = __ldg(g_aabb + b*6 + 2);
    float hix = __ldg(g_aabb + b*6 + 3), hiy = __ldg(g_aabb + b*6 + 4), hiz = __ldg(g_aabb + b*6 + 5);
    float epl = __expf(__ldg(g_pls));

    // ---- B tables: word m covers features (2m, 2m+1); perm: xz 0..63, pick 64..66, pose 67..78, 79=0
    for (int e = tid; e < 640; e += 256){
        int m = e / 16, n = e & 15;
        float w0 = 0.f, w1 = 0.f;
        {
            int k = 2*m;
            if (k < 79){ int f = (k < 64) ? k + 3 : ((k < 67) ? k - 64 : k); w0 = __ldg(g_w1 + f*16 + n); }
            k = 2*m + 1;
            if (k < 79){ int f = (k < 64) ? k + 3 : ((k < 67) ? k - 64 : k); w1 = __ldg(g_w1 + f*16 + n); }
        }
        __half h0 = __float2half_rn(w0), h1 = __float2half_rn(w1);
        float l0 = (w0 - __half2float(h0)) * 2048.f;
        float l1 = (w1 - __half2float(h1)) * 2048.f;
        uint16_t u0 = *(uint16_t*)&h0, u1 = *(uint16_t*)&h1;
        s_b1[m*BSTR + n] = (uint32_t)u0 | ((uint32_t)u1 << 16);
        s_b2[m*BSTR + n] = pack2(l0, l1);
    }
    __syncthreads();   // only the shared tables need block scope

    // ---- warp-private gather: one LDG.64 per row, pack to half2 ----
    const float* xzb = g_xz + ((size_t)b << 15);
    #pragma unroll
    for (int r = 0; r < 32; r++){
        int ir = __shfl_sync(FULL, idx, r);
        float2 xv = __ldcs((const float2*)(xzb + (ir << 6)) + lane);
        szw[r*ZS + lane] = pack2(xv.x, xv.y);
    }

    // ---- pose features -> words 32..39 (row = lane) ----
    {
        float rn = rsqrtf(qx*qx + qy*qy + qz*qz + qw*qw);
        qx *= rn; qy *= rn; qz *= rn; qw *= rn;
        float r00 = 1.f - 2.f*(qy*qy + qz*qz), r01 = 2.f*(qx*qy - qz*qw), r02 = 2.f*(qx*qz + qy*qw);
        float r10 = 2.f*(qx*qy + qz*qw), r11 = 1.f - 2.f*(qx*qx + qz*qz), r12 = 2.f*(qy*qz - qx*qw);
        float r20 = 2.f*(qx*qz - qy*qw), r21 = 2.f*(qy*qz + qx*qw), r22 = 1.f - 2.f*(qx*qx + qy*qy);
        float ci = (float)(idx >> 6) + 0.5f, cj = (float)((idx >> 3) & 7) + 0.5f, ck = (float)(idx & 7) + 0.5f;
        float vx = (ci*0.125f)*(hix - lox) + lox;
        float vy = (cj*0.125f)*(hiy - loy) + loy;
        float vz = (ck*0.125f)*(hiz - loz) + loz;
        uint32_t* prow = szw + lane*ZS;
        prow[32] = pack2(r00*vx + r01*vy + r02*vz + px, r10*vx + r11*vy + r12*vz + py);
        prow[33] = pack2(r20*vx + r21*vy + r22*vz + pz, px*epl);
        prow[34] = pack2(py*epl, pz*epl);
        prow[35] = pack2(r00, r01);
        prow[36] = pack2(r02, r10);
        prow[37] = pack2(r11, r12);
        prow[38] = pack2(r20, r21);
        prow[39] = pack2(r22, 0.f);
    }
    __syncwarp(FULL);

    // ---- fp16 MMA: 5 chunks x 2 mt x 2 nt x 2 passes = 40 MMAs ----
    float dA[2][2][4], dB[2][2][4];
    #pragma unroll
    for (int mt = 0; mt < 2; mt++)
        #pragma unroll
        for (int nt = 0; nt < 2; nt++)
            #pragma unroll
            for (int q = 0; q < 4; q++){ dA[mt][nt][q] = 0.f; dB[mt][nt][q] = 0.f; }

    #pragma unroll
    for (int k0 = 0; k0 < 5; k0++){
        const int w0i = k0*8 + j;
        uint32_t b1f[2][2], b2f[2][2];
        #pragma unroll
        for (int nt = 0; nt < 2; nt++){
            b1f[nt][0] = s_b1[(w0i  )*BSTR + nt*8 + gr];
            b1f[nt][1] = s_b1[(w0i+4)*BSTR + nt*8 + gr];
            b2f[nt][0] = s_b2[(w0i  )*BSTR + nt*8 + gr];
            b2f[nt][1] = s_b2[(w0i+4)*BSTR + nt*8 + gr];
        }
        #pragma unroll
        for (int mt = 0; mt < 2; mt++){
            const uint32_t* base = szw + (mt*16 + gr)*ZS + w0i;
            uint32_t a[4] = { base[0], base[8*ZS], base[4], base[8*ZS + 4] };
            #pragma unroll
            for (int nt = 0; nt < 2; nt++){
                mma16(dA[mt][nt], a, b1f[nt]);
                mma16(dB[mt][nt], a, b2f[nt]);
            }
        }
    }

    float d[2][2][4];
    #pragma unroll
    for (int mt = 0; mt < 2; mt++)
        #pragma unroll
        for (int nt = 0; nt < 2; nt++)
            #pragma unroll
            for (int q = 0; q < 4; q++)
                d[mt][nt][q] = dA[mt][nt][q] + dB[mt][nt][q] * (1.f/2048.f);

    // ---- epilogue: bias + relu + parallel-LN(16) per sample, x2, sum over samples ----
    float b1v[4] = { __ldg(g_b1 + 2*j),  __ldg(g_b1 + 2*j + 1),
                     __ldg(g_b1 + 8 + 2*j), __ldg(g_b1 + 9 + 2*j) };
    float g1v[4] = { __ldg(g_g1 + 2*j),  __ldg(g_g1 + 2*j + 1),
                     __ldg(g_g1 + 8 + 2*j), __ldg(g_g1 + 9 + 2*j) };
    float be1v[4] = { __ldg(g_be1 + 2*j), __ldg(g_be1 + 2*j + 1),
                      __ldg(g_be1 + 8 + 2*j), __ldg(g_be1 + 9 + 2*j) };

    float vsum[4] = {0.f, 0.f, 0.f, 0.f};
    #pragma unroll
    for (int mt = 0; mt < 2; mt++){
        #pragma unroll
        for (int rl = 0; rl < 2; rl++){
            float y0 = fmaxf(d[mt][0][rl*2]   + b1v[0], 0.f);
            float y1 = fmaxf(d[mt][0][rl*2+1] + b1v[1], 0.f);
            float y2 = fmaxf(d[mt][1][rl*2]   + b1v[2], 0.f);
            float y3 = fmaxf(d[mt][1][rl*2+1] + b1v[3], 0.f);
            float s  = (y0 + y1) + (y2 + y3);
            float t2 = (y0*y0 + y1*y1) + (y2*y2 + y3*y3);
            s  += __shfl_xor_sync(FULL, s, 1);   t2 += __shfl_xor_sync(FULL, t2, 1);
            s  += __shfl_xor_sync(FULL, s, 2);   t2 += __shfl_xor_sync(FULL, t2, 2);
            float m   = s * 0.0625f;
            float var = t2 * 0.0625f - m*m;
            float is2 = 2.f * rsqrtf(var + 1e-6f);   // LN then z+z
            vsum[0] += (y0 - m) * is2 * g1v[0] + 2.f*be1v[0];
            vsum[1] += (y1 - m) * is2 * g1v[1] + 2.f*be1v[1];
            vsum[2] += (y2 - m) * is2 * g1v[2] + 2.f*be1v[2];
            vsum[3] += (y3 - m) * is2 * g1v[3] + 2.f*be1v[3];
        }
    }
    #pragma unroll
    for (int c = 0; c < 4; c++){
        vsum[c] += __shfl_xor_sync(FULL, vsum[c], 4);
        vsum[c] += __shfl_xor_sync(FULL, vsum[c], 8);
        vsum[c] += __shfl_xor_sync(FULL, vsum[c], 16);
    }
    if (gr == 0){
        float* sv = s_v + warp*16;
        sv[2*j]     = vsum[0];
        sv[2*j + 1] = vsum[1];
        sv[8 + 2*j] = vsum[2];
        sv[9 + 2*j] = vsum[3];
    }
    __syncwarp(FULL);
    float v[16];
    #pragma unroll
    for (int t = 0; t < 4; t++){
        float4 s4 = *(const float4*)(s_v + warp*16 + 4*t);
        v[4*t] = s4.x; v[4*t+1] = s4.y; v[4*t+2] = s4.z; v[4*t+3] = s4.w;
    }

    // ---- head: lane = channel, parallel-LN ----
    {
        float a0 = __ldg(g_b2a + lane), a1 = 0.f, a2 = 0.f, a3 = 0.f;
        #pragma unroll
        for (int i = 0; i < 16; i += 4){
            a0 = fmaf(v[i+0], __ldg(g_w2a + (i+0)*32 + lane), a0);
            a1 = fmaf(v[i+1], __ldg(g_w2a + (i+1)*32 + lane), a1);
            a2 = fmaf(v[i+2], __ldg(g_w2a + (i+2)*32 + lane), a2);
            a3 = fmaf(v[i+3], __ldg(g_w2a + (i+3)*32 + lane), a3);
        }
        float a = (a0 + a1) + (a2 + a3);
        a = fmaxf(a, 0.f);
        float s1 = a, s2 = a*a;
        wsum2(s1, s2);
        float ma = s1 * 0.03125f;
        float va = s2 * 0.03125f - ma*ma;
        float ya = (a - ma) * rsqrtf(va + 1e-6f) * __ldg(g_g2a + lane) + __ldg(g_be2a + lane);

        float c0 = __ldg(g_b2b + lane), c1 = 0.f, c2 = 0.f, c3 = 0.f;
        #pragma unroll
        for (int i = 0; i < 32; i += 4){
            c0 = fmaf(__shfl_sync(FULL, ya, i+0), __ldg(g_w2b + (i+0)*32 + lane), c0);
            c1 = fmaf(__shfl_sync(FULL, ya, i+1), __ldg(g_w2b + (i+1)*32 + lane), c1);
            c2 = fmaf(__shfl_sync(FULL, ya, i+2), __ldg(g_w2b + (i+2)*32 + lane), c2);
            c3 = fmaf(__shfl_sync(FULL, ya, i+3), __ldg(g_w2b + (i+3)*32 + lane), c3);
        }
        float c = (c0 + c1) + (c2 + c3);
        c = fmaxf(c, 0.f);
        float u1 = c, u2 = c*c;
        wsum2(u1, u2);
        float mc = u1 * 0.03125f;
        float vc = u2 * 0.03125f - mc*mc;
        float yb = (c - mc) * rsqrtf(vc + 1e-6f) * __ldg(g_g2b + lane) + __ldg(g_be2b + lane);
        float zf = yb + ya;   // residual

        float o0 = (lane < 13) ? __ldg(g_bout + lane) : 0.f;
        float o1 = 0.f;
        #pragma unroll
        for (int i = 0; i < 32; i += 2){
            float zi0 = __shfl_sync(FULL, zf, i);
            float zi1 = __shfl_sync(FULL, zf, i+1);
            if (lane < 13){
                o0 = fmaf(zi0, __ldg(g_wout + (i  )*13 + lane), o0);
                o1 = fmaf(zi1, __ldg(g_wout + (i+1)*13 + lane), o1);
            }
        }
        if (lane < 13) g_out[b*13 + lane] = tanhf(o0 + o1);
    }
}

extern "C" void kernel_launch(void* const* d_in, const int* in_sizes, int n_in,
                              void* d_out, int out_size)
{
    (void)in_sizes; (void)n_in; (void)out_size;
    const int SMEM_BYTES = (40*BSTR*2 + 128 + 8*32*ZS) * 4;   // ~53.2 KB -> 4 blocks/SM
    cudaFuncSetAttribute(plane_kernel,
                         cudaFuncAttributeMaxDynamicSharedMemorySize, SMEM_BYTES);
    plane_kernel<<<1024, 256, SMEM_BYTES>>>(
        (const float*)d_in[0],  (const float*)d_in[1],  (const float*)d_in[2],
        (const float*)d_in[3],  (const int*)  d_in[4],  (const float*)d_in[5],
        (const float*)d_in[6],  (const float*)d_in[7],  (const float*)d_in[8],
        (const float*)d_in[9],  (const float*)d_in[10], (const float*)d_in[11],
        (const float*)d_in[12], (const float*)d_in[13], (const float*)d_in[14],
        (const float*)d_in[15], (const float*)d_in[16], (const float*)d_in[17],
        (const float*)d_in[18], (const float*)d_in[19],
        (float*)d_out);
}

// round 15
// speedup vs baseline: 1.5714x; 1.0679x over previous
#include <cuda_runtime.h>
#include <cuda_fp16.h>
#include <cstdint>

// PlaneModel: B=8192, NS=32, P=64, HID1=16, BASE=32, OUT=13, D_IN=79
// Layer-1 GEMV on mma.sync m16n8k16 fp16 (true K=80, 5 chunks), fp32 accum.
// A = fp16 pairs; B = whi + wlo*2^11 (2 passes, recombined dA + dB/2048).
// warp = batch. LDG.128 gather (2 rows/instr). ZS=44 -> 53KB smem -> 4 blocks/SM.
#define FULL 0xffffffffu
#define ZS 44        // word stride: (12*gr + j) mod 32 all-distinct -> conflict-free frag reads
#define BSTR 24      // B table stride: conflict-free frag reads

__device__ __forceinline__ uint32_t pack2(float x, float y){
    __half2 h = __floats2half2_rn(x, y);
    return *(uint32_t*)&h;
}
__device__ __forceinline__ void mma16(float* d, const uint32_t* a, const uint32_t* b){
    asm volatile("mma.sync.aligned.m16n8k16.row.col.f32.f16.f16.f32 "
        "{%0,%1,%2,%3},{%4,%5,%6,%7},{%8,%9},{%0,%1,%2,%3};"
        : "+f"(d[0]), "+f"(d[1]), "+f"(d[2]), "+f"(d[3])
        : "r"(a[0]), "r"(a[1]), "r"(a[2]), "r"(a[3]), "r"(b[0]), "r"(b[1]));
}
__device__ __forceinline__ void wsum2(float& x, float& y){
    x += __shfl_xor_sync(FULL, x, 16);  y += __shfl_xor_sync(FULL, y, 16);
    x += __shfl_xor_sync(FULL, x, 8);   y += __shfl_xor_sync(FULL, y, 8);
    x += __shfl_xor_sync(FULL, x, 4);   y += __shfl_xor_sync(FULL, y, 4);
    x += __shfl_xor_sync(FULL, x, 2);   y += __shfl_xor_sync(FULL, y, 2);
    x += __shfl_xor_sync(FULL, x, 1);   y += __shfl_xor_sync(FULL, y, 1);
}

__global__ void __launch_bounds__(256)
plane_kernel(const float* __restrict__ g_pos,  const float* __restrict__ g_quat,
             const float* __restrict__ g_xz,   const float* __restrict__ g_aabb,
             const int*   __restrict__ g_widx, const float* __restrict__ g_pls,
             const float* __restrict__ g_w1,   const float* __restrict__ g_b1,
             const float* __restrict__ g_g1,   const float* __restrict__ g_be1,
             const float* __restrict__ g_w2a,  const float* __restrict__ g_b2a,
             const float* __restrict__ g_g2a,  const float* __restrict__ g_be2a,
             const float* __restrict__ g_w2b,  const float* __restrict__ g_b2b,
             const float* __restrict__ g_g2b,  const float* __restrict__ g_be2b,
             const float* __restrict__ g_wout, const float* __restrict__ g_bout,
             float* __restrict__ g_out)
{
    extern __shared__ __align__(16) uint32_t smw[];
    uint32_t* s_b1 = smw;               // 40*24 packed (whi pairs) [word][n]
    uint32_t* s_b2 = s_b1 + 40*BSTR;    // 40*24 packed (wlo*2^11 pairs)
    float*    s_v  = (float*)(s_b2 + 40*BSTR);   // 8*16 per-warp layer-1 sums
    uint32_t* s_z  = (uint32_t*)(s_v + 128);     // 8 * 32*ZS packed A words

    const int tid  = threadIdx.x;
    const int warp = tid >> 5, lane = tid & 31;
    const int j    = lane & 3;
    const int gr   = lane >> 2;
    const int b    = (blockIdx.x << 3) + warp;
    uint32_t* szw = s_z + warp*(32*ZS);

    // ---- prefetch per-batch scalars ----
    const int idx = __ldg(g_widx + b*32 + lane);
    float qx = __ldg(g_quat + b*4 + 0), qy = __ldg(g_quat + b*4 + 1);
    float qz = __ldg(g_quat + b*4 + 2), qw = __ldg(g_quat + b*4 + 3);
    float px = __ldg(g_pos + b*3 + 0), py = __ldg(g_pos + b*3 + 1), pz = __ldg(g_pos + b*3 + 2);
    float lox = __ldg(g_aabb + b*6 + 0), loy = __ldg(g_aabb + b*6 + 1), loz = __ldg(g_aabb + b*6 + 2);
    float hix = __ldg(g_aabb + b*6 + 3), hiy = __ldg(g_aabb + b*6 + 4), hiz = __ldg(g_aabb + b*6 + 5);
    float epl = __expf(__ldg(g_pls));

    // ---- B tables: word m covers features (2m, 2m+1); perm: xz 0..63, pick 64..66, pose 67..78, 79=0
    for (int e = tid; e < 640; e += 256){
        int m = e / 16, n = e & 15;
        float w0 = 0.f, w1 = 0.f;
        {
            int k = 2*m;
            if (k < 79){ int f = (k < 64) ? k + 3 : ((k < 67) ? k - 64 : k); w0 = __ldg(g_w1 + f*16 + n); }
            k = 2*m + 1;
            if (k < 79){ int f = (k < 64) ? k + 3 : ((k < 67) ? k - 64 : k); w1 = __ldg(g_w1 + f*16 + n); }
        }
        __half h0 = __float2half_rn(w0), h1 = __float2half_rn(w1);
        float l0 = (w0 - __half2float(h0)) * 2048.f;
        float l1 = (w1 - __half2float(h1)) * 2048.f;
        uint16_t u0 = *(uint16_t*)&h0, u1 = *(uint16_t*)&h1;
        s_b1[m*BSTR + n] = (uint32_t)u0 | ((uint32_t)u1 << 16);
        s_b2[m*BSTR + n] = pack2(l0, l1);
    }
    __syncthreads();   // only the shared tables need block scope

    // ---- warp-private gather: LDG.128, 2 rows per instruction ----
    // lane = (row parity 'half', 16B chunk c): rows 2i+half, words 2c,2c+1
    const float* xzb = g_xz + ((size_t)b << 15);
    {
        const int half = lane >> 4;      // 0 or 1
        const int c    = lane & 15;      // float4 chunk 0..15
        #pragma unroll
        for (int i = 0; i < 16; i++){
            int r  = 2*i + half;
            int ir = __shfl_sync(FULL, idx, r);
            float4 xv = __ldcs((const float4*)(xzb + (ir << 6)) + c);
            uint32_t w0 = pack2(xv.x, xv.y);
            uint32_t w1 = pack2(xv.z, xv.w);
            *(uint2*)(szw + r*ZS + 2*c) = make_uint2(w0, w1);   // STS.64, conflict-free
        }
    }

    // ---- pose features -> words 32..39 (row = lane) ----
    {
        float rn = rsqrtf(qx*qx + qy*qy + qz*qz + qw*qw);
        qx *= rn; qy *= rn; qz *= rn; qw *= rn;
        float r00 = 1.f - 2.f*(qy*qy + qz*qz), r01 = 2.f*(qx*qy - qz*qw), r02 = 2.f*(qx*qz + qy*qw);
        float r10 = 2.f*(qx*qy + qz*qw), r11 = 1.f - 2.f*(qx*qx + qz*qz), r12 = 2.f*(qy*qz - qx*qw);
        float r20 = 2.f*(qx*qz - qy*qw), r21 = 2.f*(qy*qz + qx*qw), r22 = 1.f - 2.f*(qx*qx + qy*qy);
        float ci = (float)(idx >> 6) + 0.5f, cj = (float)((idx >> 3) & 7) + 0.5f, ck = (float)(idx & 7) + 0.5f;
        float vx = (ci*0.125f)*(hix - lox) + lox;
        float vy = (cj*0.125f)*(hiy - loy) + loy;
        float vz = (ck*0.125f)*(hiz - loz) + loz;
        uint32_t* prow = szw + lane*ZS;
        prow[32] = pack2(r00*vx + r01*vy + r02*vz + px, r10*vx + r11*vy + r12*vz + py);
        prow[33] = pack2(r20*vx + r21*vy + r22*vz + pz, px*epl);
        prow[34] = pack2(py*epl, pz*epl);
        prow[35] = pack2(r00, r01);
        prow[36] = pack2(r02, r10);
        prow[37] = pack2(r11, r12);
        prow[38] = pack2(r20, r21);
        prow[39] = pack2(r22, 0.f);
    }
    __syncwarp(FULL);

    // ---- fp16 MMA: 5 chunks x 2 mt x 2 nt x 2 passes = 40 MMAs ----
    float dA[2][2][4], dB[2][2][4];
    #pragma unroll
    for (int mt = 0; mt < 2; mt++)
        #pragma unroll
        for (int nt = 0; nt < 2; nt++)
            #pragma unroll
            for (int q = 0; q < 4; q++){ dA[mt][nt][q] = 0.f; dB[mt][nt][q] = 0.f; }

    #pragma unroll
    for (int k0 = 0; k0 < 5; k0++){
        const int w0i = k0*8 + j;
        uint32_t b1f[2][2], b2f[2][2];
        #pragma unroll
        for (int nt = 0; nt < 2; nt++){
            b1f[nt][0] = s_b1[(w0i  )*BSTR + nt*8 + gr];
            b1f[nt][1] = s_b1[(w0i+4)*BSTR + nt*8 + gr];
            b2f[nt][0] = s_b2[(w0i  )*BSTR + nt*8 + gr];
            b2f[nt][1] = s_b2[(w0i+4)*BSTR + nt*8 + gr];
        }
        #pragma unroll
        for (int mt = 0; mt < 2; mt++){
            const uint32_t* base = szw + (mt*16 + gr)*ZS + w0i;
            uint32_t a[4] = { base[0], base[8*ZS], base[4], base[8*ZS + 4] };
            #pragma unroll
            for (int nt = 0; nt < 2; nt++){
                mma16(dA[mt][nt], a, b1f[nt]);
                mma16(dB[mt][nt], a, b2f[nt]);
            }
        }
    }

    float d[2][2][4];
    #pragma unroll
    for (int mt = 0; mt < 2; mt++)
        #pragma unroll
        for (int nt = 0; nt < 2; nt++)
            #pragma unroll
            for (int q = 0; q < 4; q++)
                d[mt][nt][q] = dA[mt][nt][q] + dB[mt][nt][q] * (1.f/2048.f);

    // ---- epilogue: bias + relu + parallel-LN(16) per sample, x2, sum over samples ----
    float b1v[4] = { __ldg(g_b1 + 2*j),  __ldg(g_b1 + 2*j + 1),
                     __ldg(g_b1 + 8 + 2*j), __ldg(g_b1 + 9 + 2*j) };
    float g1v[4] = { __ldg(g_g1 + 2*j),  __ldg(g_g1 + 2*j + 1),
                     __ldg(g_g1 + 8 + 2*j), __ldg(g_g1 + 9 + 2*j) };
    float be1v[4] = { __ldg(g_be1 + 2*j), __ldg(g_be1 + 2*j + 1),
                      __ldg(g_be1 + 8 + 2*j), __ldg(g_be1 + 9 + 2*j) };

    float vsum[4] = {0.f, 0.f, 0.f, 0.f};
    #pragma unroll
    for (int mt = 0; mt < 2; mt++){
        #pragma unroll
        for (int rl = 0; rl < 2; rl++){
            float y0 = fmaxf(d[mt][0][rl*2]   + b1v[0], 0.f);
            float y1 = fmaxf(d[mt][0][rl*2+1] + b1v[1], 0.f);
            float y2 = fmaxf(d[mt][1][rl*2]   + b1v[2], 0.f);
            float y3 = fmaxf(d[mt][1][rl*2+1] + b1v[3], 0.f);
            float s  = (y0 + y1) + (y2 + y3);
            float t2 = (y0*y0 + y1*y1) + (y2*y2 + y3*y3);
            s  += __shfl_xor_sync(FULL, s, 1);   t2 += __shfl_xor_sync(FULL, t2, 1);
            s  += __shfl_xor_sync(FULL, s, 2);   t2 += __shfl_xor_sync(FULL, t2, 2);
            float m   = s * 0.0625f;
            float var = t2 * 0.0625f - m*m;
            float is2 = 2.f * rsqrtf(var + 1e-6f);   // LN then z+z
            vsum[0] += (y0 - m) * is2 * g1v[0] + 2.f*be1v[0];
            vsum[1] += (y1 - m) * is2 * g1v[1] + 2.f*be1v[1];
            vsum[2] += (y2 - m) * is2 * g1v[2] + 2.f*be1v[2];
            vsum[3] += (y3 - m) * is2 * g1v[3] + 2.f*be1v[3];
        }
    }
    #pragma unroll
    for (int c = 0; c < 4; c++){
        vsum[c] += __shfl_xor_sync(FULL, vsum[c], 4);
        vsum[c] += __shfl_xor_sync(FULL, vsum[c], 8);
        vsum[c] += __shfl_xor_sync(FULL, vsum[c], 16);
    }
    if (gr == 0){
        float* sv = s_v + warp*16;
        sv[2*j]     = vsum[0];
        sv[2*j + 1] = vsum[1];
        sv[8 + 2*j] = vsum[2];
        sv[9 + 2*j] = vsum[3];
    }
    __syncwarp(FULL);
    float v[16];
    #pragma unroll
    for (int t = 0; t < 4; t++){
        float4 s4 = *(const float4*)(s_v + warp*16 + 4*t);
        v[4*t] = s4.x; v[4*t+1] = s4.y; v[4*t+2] = s4.z; v[4*t+3] = s4.w;
    }

    // ---- head: lane = channel, parallel-LN ----
    {
        float a0 = __ldg(g_b2a + lane), a1 = 0.f, a2 = 0.f, a3 = 0.f;
        #pragma unroll
        for (int i = 0; i < 16; i += 4){
            a0 = fmaf(v[i+0], __ldg(g_w2a + (i+0)*32 + lane), a0);
            a1 = fmaf(v[i+1], __ldg(g_w2a + (i+1)*32 + lane), a1);
            a2 = fmaf(v[i+2], __ldg(g_w2a + (i+2)*32 + lane), a2);
            a3 = fmaf(v[i+3], __ldg(g_w2a + (i+3)*32 + lane), a3);
        }
        float a = (a0 + a1) + (a2 + a3);
        a = fmaxf(a, 0.f);
        float s1 = a, s2 = a*a;
        wsum2(s1, s2);
        float ma = s1 * 0.03125f;
        float va = s2 * 0.03125f - ma*ma;
        float ya = (a - ma) * rsqrtf(va + 1e-6f) * __ldg(g_g2a + lane) + __ldg(g_be2a + lane);

        float c0 = __ldg(g_b2b + lane), c1 = 0.f, c2 = 0.f, c3 = 0.f;
        #pragma unroll
        for (int i = 0; i < 32; i += 4){
            c0 = fmaf(__shfl_sync(FULL, ya, i+0), __ldg(g_w2b + (i+0)*32 + lane), c0);
            c1 = fmaf(__shfl_sync(FULL, ya, i+1), __ldg(g_w2b + (i+1)*32 + lane), c1);
            c2 = fmaf(__shfl_sync(FULL, ya, i+2), __ldg(g_w2b + (i+2)*32 + lane), c2);
            c3 = fmaf(__shfl_sync(FULL, ya, i+3), __ldg(g_w2b + (i+3)*32 + lane), c3);
        }
        float c = (c0 + c1) + (c2 + c3);
        c = fmaxf(c, 0.f);
        float u1 = c, u2 = c*c;
        wsum2(u1, u2);
        float mc = u1 * 0.03125f;
        float vc = u2 * 0.03125f - mc*mc;
        float yb = (c - mc) * rsqrtf(vc + 1e-6f) * __ldg(g_g2b + lane) + __ldg(g_be2b + lane);
        float zf = yb + ya;   // residual

        float o0 = (lane < 13) ? __ldg(g_bout + lane) : 0.f;
        float o1 = 0.f;
        #pragma unroll
        for (int i = 0; i < 32; i += 2){
            float zi0 = __shfl_sync(FULL, zf, i);
            float zi1 = __shfl_sync(FULL, zf, i+1);
            if (lane < 13){
                o0 = fmaf(zi0, __ldg(g_wout + (i  )*13 + lane), o0);
                o1 = fmaf(zi1, __ldg(g_wout + (i+1)*13 + lane), o1);
            }
        }
        if (lane < 13) g_out[b*13 + lane] = tanhf(o0 + o1);
    }
}

extern "C" void kernel_launch(void* const* d_in, const int* in_sizes, int n_in,
                              void* d_out, int out_size)
{
    (void)in_sizes; (void)n_in; (void)out_size;
    const int SMEM_BYTES = (40*BSTR*2 + 128 + 8*32*ZS) * 4;   // ~53.2 KB -> 4 blocks/SM
    cudaFuncSetAttribute(plane_kernel,
                         cudaFuncAttributeMaxDynamicSharedMemorySize, SMEM_BYTES);
    plane_kernel<<<1024, 256, SMEM_BYTES>>>(
        (const float*)d_in[0],  (const float*)d_in[1],  (const float*)d_in[2],
        (const float*)d_in[3],  (const int*)  d_in[4],  (const float*)d_in[5],
        (const float*)d_in[6],  (const float*)d_in[7],  (const float*)d_in[8],
        (const float*)d_in[9],  (const float*)d_in[10], (const float*)d_in[11],
        (const float*)d_in[12], (const float*)d_in[13], (const float*)d_in[14],
        (const float*)d_in[15], (const float*)d_in[16], (const float*)d_in[17],
        (const float*)d_in[18], (const float*)d_in[19],
        (float*)d_out);
}